// round 7
// baseline (speedup 1.0000x reference)
#include <cuda_runtime.h>

// Output (64, 64, 62, 62) f32, batch slice = 246016 floats = 61504 float4.
// Only out[b, 0, 0:2, 0:62] (first 124 floats = 31 f4) of each batch is
// nonzero. Zero region per batch: f4 [31, 61504).
//   fill blocks: 120 per batch, 512 thr, ONE unconditional f4 streaming
//                store each -> cover f4 [31, 61471) per batch.
//   strip blocks (0..30): threads 0..63 compute the Winograd strip for tile
//                u = blockIdx.x; threads 64..255 zero the per-batch tails
//                f4 [61471, 61504) (64 batches x 33 f4 = 2112 stores).
// All write sets disjoint -> single kernel, no races.

#define NSTRIP    31
#define BATCH_F4  61504
#define FILL_BASE 31        // first zeroed f4 in each batch
#define FPB       120       // fill blocks per batch (512 thr each)
#define TAIL_F4   33        // 61504 - 31 - 120*512
#define TAIL_BEG  61471     // 31 + 120*512
#define NTAIL     (64 * TAIL_F4)   // 2112

__global__ void __launch_bounds__(512)
wg_fused(const float* __restrict__ x,
         const float* __restrict__ filt,
         float* __restrict__ out) {
    if (blockIdx.x >= NSTRIP) {
        // ---------- fill path: one unconditional 16B streaming store ----------
        const int zb    = blockIdx.x - NSTRIP;
        const int batch = zb / FPB;
        const int chunk = zb - batch * FPB;
        float4* o4 = (float4*)out;
        __stcs(&o4[(size_t)batch * BATCH_F4 + FILL_BASE + chunk * 512 + threadIdx.x],
               make_float4(0.f, 0.f, 0.f, 0.f));
        return;
    }

    // ---------------- strip + tail block: tile u = blockIdx.x --------------
    const int u = blockIdx.x;
    __shared__ float sm[2][16];
    __shared__ float Y[4];

    if (threadIdx.x >= 64) {
        // tail zeroing with the spare threads (threads 64..255 used)
        const int spare = threadIdx.x - 64;
        if (spare < 192) {
            const int idx = u * 192 + spare;
            if (idx < NTAIL) {
                const int batch = idx / TAIL_F4;
                const int slot  = idx - batch * TAIL_F4;
                __stcs(&((float4*)out)[(size_t)batch * BATCH_F4 + TAIL_BEG + slot],
                       make_float4(0.f, 0.f, 0.f, 0.f));
            }
        }
    } else {
        const int c = threadIdx.x;  // channel 0..63

        // W = filters[0, c]
        float W[3][3];
#pragma unroll
        for (int j = 0; j < 3; ++j)
#pragma unroll
            for (int k = 0; k < 3; ++k)
                W[j][k] = filt[c * 9 + j * 3 + k];

        // U = G W G^T,  G = [[1,0,0],[.5,.5,1.2],[.5,-.5,.5],[0,0,1]]
        float s[4][3];
#pragma unroll
        for (int k = 0; k < 3; ++k) {
            s[0][k] = W[0][k];
            s[1][k] = 0.5f * W[0][k] + 0.5f * W[1][k] + 1.2f * W[2][k];
            s[2][k] = 0.5f * W[0][k] - 0.5f * W[1][k] + 0.5f * W[2][k];
            s[3][k] = W[2][k];
        }
        float U[4][4];
#pragma unroll
        for (int i = 0; i < 4; ++i) {
            U[i][0] = s[i][0];
            U[i][1] = 0.5f * s[i][0] + 0.5f * s[i][1] + 1.2f * s[i][2];
            U[i][2] = 0.5f * s[i][0] - 0.5f * s[i][1] + 0.5f * s[i][2];
            U[i][3] = s[i][2];
        }

        // X = x[0, c, 0:4, 2u:2u+4]
        float X[4][4];
        const float* xp = x + c * 4096 + 2 * u;
#pragma unroll
        for (int j = 0; j < 4; ++j)
#pragma unroll
            for (int k = 0; k < 4; ++k)
                X[j][k] = xp[j * 64 + k];

        // t = B^T X ; B^T rows: (1,0,0,0) (0,1,-1,1) (-1,1,1,0) (0,0,0,-1)
        float t[4][4];
#pragma unroll
        for (int k = 0; k < 4; ++k) {
            t[0][k] = X[0][k];
            t[1][k] = X[1][k] - X[2][k] + X[3][k];
            t[2][k] = -X[0][k] + X[1][k] + X[2][k];
            t[3][k] = -X[3][k];
        }
        // V = t B ; M_c = U .* V ; accumulate over channels
        float Macc[16];
#pragma unroll
        for (int i = 0; i < 4; ++i) {
            float v0 = t[i][0];
            float v1 = t[i][1] - t[i][2] + t[i][3];
            float v2 = -t[i][0] + t[i][1] + t[i][2];
            float v3 = -t[i][3];
            Macc[i * 4 + 0] = U[i][0] * v0;
            Macc[i * 4 + 1] = U[i][1] * v1;
            Macc[i * 4 + 2] = U[i][2] * v2;
            Macc[i * 4 + 3] = U[i][3] * v3;
        }

        // reduce 16 values over 64 channels (2 warps)
#pragma unroll
        for (int off = 16; off > 0; off >>= 1)
#pragma unroll
            for (int e = 0; e < 16; ++e)
                Macc[e] += __shfl_down_sync(0xffffffffu, Macc[e], off);

        const int warp = threadIdx.x >> 5;
        const int lane = threadIdx.x & 31;
        if (lane == 0) {
#pragma unroll
            for (int e = 0; e < 16; ++e) sm[warp][e] = Macc[e];
        }
    }
    __syncthreads();
    if (threadIdx.x == 0) {
        float M[4][4];
#pragma unroll
        for (int e = 0; e < 16; ++e) M[e >> 2][e & 3] = sm[0][e] + sm[1][e];
        // Y = AT M AT^T ; AT = [[1,1,1,0],[0,1,-1,-1]]
        float T0[4], T1[4];
#pragma unroll
        for (int k = 0; k < 4; ++k) {
            T0[k] = M[0][k] + M[1][k] + M[2][k];
            T1[k] = M[1][k] - M[2][k] - M[3][k];
        }
        Y[0] = T0[0] + T0[1] + T0[2];
        Y[1] = T0[1] - T0[2] - T0[3];
        Y[2] = T1[0] + T1[1] + T1[2];
        Y[3] = T1[1] - T1[2] - T1[3];
    }
    __syncthreads();

    // fan out: out[b, 0, {0,1}, 2u + {0,1}] for all 64 batches (float2 stores)
    if (threadIdx.x < 64) {
        const int b = threadIdx.x;
        float* op = out + (size_t)b * 246016 + 2 * u;
        *(float2*)(op)      = make_float2(Y[0], Y[1]);
        *(float2*)(op + 62) = make_float2(Y[2], Y[3]);
    }
}

extern "C" void kernel_launch(void* const* d_in, const int* in_sizes, int n_in,
                              void* d_out, int out_size) {
    const float* x    = (const float*)d_in[0];   // (64,64,64,64) f32
    const float* filt = (const float*)d_in[1];   // (64,64,3,3)   f32
    float* out = (float*)d_out;                  // (64,64,62,62) f32

    const int nblocks = NSTRIP + FPB * 64;       // 31 + 7680 = 7711
    wg_fused<<<nblocks, 512>>>(x, filt, out);
}

// round 8
// speedup vs baseline: 1.0827x; 1.0827x over previous
#include <cuda_runtime.h>

// Output (64, 64, 62, 62) f32, batch slice = 246016 floats = 61504 float4.
// Only out[b, 0, 0:2, 0:62] (first 124 floats = 31 f4) of each batch is
// nonzero. Zero region per batch: f4 [31, 61504).
//
// Grid (241, 64), 256 threads. batch = blockIdx.y (no div/mod anywhere).
//   x in [0,240): fill — one UNCONDITIONAL f4 store, covers f4 [31, 61471).
//   x == 240    : threads 64..96 zero this batch's tail f4 [61471, 61504);
//                 threads 0..63 compute the Winograd strip for tile u = y
//                 (only for y < 31; tiles are 0..30).
// Write sets disjoint -> one kernel, no races.

#define BATCH_F4  61504
#define FILL_BASE 31
#define FPB       240       // fill blocks per batch
#define TAIL_F4   33        // 61504 - 31 - 240*256
#define TAIL_BEG  61471

__global__ void __launch_bounds__(256)
wg_fused(const float* __restrict__ x,
         const float* __restrict__ filt,
         float* __restrict__ out) {
    const int batch = blockIdx.y;

    if (blockIdx.x < FPB) {
        // -------- fill path: one unconditional 16B store, IMAD-only addr ----
        ((float4*)out)[(size_t)batch * BATCH_F4 + FILL_BASE
                       + blockIdx.x * 256 + threadIdx.x] =
            make_float4(0.f, 0.f, 0.f, 0.f);
        return;
    }

    // ---------------- x == 240: tail + strip block ----------------
    __shared__ float sm[2][16];
    __shared__ float Y[4];
    const int u = batch;            // strip tile index when u < 31

    if (threadIdx.x >= 64) {
        // zero this batch's 33-f4 tail with threads 64..96
        const int slot = threadIdx.x - 64;
        if (slot < TAIL_F4) {
            ((float4*)out)[(size_t)batch * BATCH_F4 + TAIL_BEG + slot] =
                make_float4(0.f, 0.f, 0.f, 0.f);
        }
    } else if (u < 31) {
        const int c = threadIdx.x;  // channel 0..63

        // W = filters[0, c]
        float W[3][3];
#pragma unroll
        for (int j = 0; j < 3; ++j)
#pragma unroll
            for (int k = 0; k < 3; ++k)
                W[j][k] = filt[c * 9 + j * 3 + k];

        // U = G W G^T,  G = [[1,0,0],[.5,.5,1.2],[.5,-.5,.5],[0,0,1]]
        float s[4][3];
#pragma unroll
        for (int k = 0; k < 3; ++k) {
            s[0][k] = W[0][k];
            s[1][k] = 0.5f * W[0][k] + 0.5f * W[1][k] + 1.2f * W[2][k];
            s[2][k] = 0.5f * W[0][k] - 0.5f * W[1][k] + 0.5f * W[2][k];
            s[3][k] = W[2][k];
        }
        float U[4][4];
#pragma unroll
        for (int i = 0; i < 4; ++i) {
            U[i][0] = s[i][0];
            U[i][1] = 0.5f * s[i][0] + 0.5f * s[i][1] + 1.2f * s[i][2];
            U[i][2] = 0.5f * s[i][0] - 0.5f * s[i][1] + 0.5f * s[i][2];
            U[i][3] = s[i][2];
        }

        // X = x[0, c, 0:4, 2u:2u+4]
        float X[4][4];
        const float* xp = x + c * 4096 + 2 * u;
#pragma unroll
        for (int j = 0; j < 4; ++j)
#pragma unroll
            for (int k = 0; k < 4; ++k)
                X[j][k] = xp[j * 64 + k];

        // t = B^T X ; B^T rows: (1,0,0,0) (0,1,-1,1) (-1,1,1,0) (0,0,0,-1)
        float t[4][4];
#pragma unroll
        for (int k = 0; k < 4; ++k) {
            t[0][k] = X[0][k];
            t[1][k] = X[1][k] - X[2][k] + X[3][k];
            t[2][k] = -X[0][k] + X[1][k] + X[2][k];
            t[3][k] = -X[3][k];
        }
        // V = t B ; M_c = U .* V ; accumulate over channels
        float Macc[16];
#pragma unroll
        for (int i = 0; i < 4; ++i) {
            float v0 = t[i][0];
            float v1 = t[i][1] - t[i][2] + t[i][3];
            float v2 = -t[i][0] + t[i][1] + t[i][2];
            float v3 = -t[i][3];
            Macc[i * 4 + 0] = U[i][0] * v0;
            Macc[i * 4 + 1] = U[i][1] * v1;
            Macc[i * 4 + 2] = U[i][2] * v2;
            Macc[i * 4 + 3] = U[i][3] * v3;
        }

        // reduce 16 values over 64 channels (2 warps)
#pragma unroll
        for (int off = 16; off > 0; off >>= 1)
#pragma unroll
            for (int e = 0; e < 16; ++e)
                Macc[e] += __shfl_down_sync(0xffffffffu, Macc[e], off);

        const int warp = threadIdx.x >> 5;
        const int lane = threadIdx.x & 31;
        if (lane == 0) {
#pragma unroll
            for (int e = 0; e < 16; ++e) sm[warp][e] = Macc[e];
        }
    }
    __syncthreads();
    if (threadIdx.x == 0 && u < 31) {
        float M[4][4];
#pragma unroll
        for (int e = 0; e < 16; ++e) M[e >> 2][e & 3] = sm[0][e] + sm[1][e];
        // Y = AT M AT^T ; AT = [[1,1,1,0],[0,1,-1,-1]]
        float T0[4], T1[4];
#pragma unroll
        for (int k = 0; k < 4; ++k) {
            T0[k] = M[0][k] + M[1][k] + M[2][k];
            T1[k] = M[1][k] - M[2][k] - M[3][k];
        }
        Y[0] = T0[0] + T0[1] + T0[2];
        Y[1] = T0[1] - T0[2] - T0[3];
        Y[2] = T1[0] + T1[1] + T1[2];
        Y[3] = T1[1] - T1[2] - T1[3];
    }
    __syncthreads();

    // fan out: out[b, 0, {0,1}, 2u + {0,1}] for all 64 batches
    if (threadIdx.x < 64 && u < 31) {
        const int b = threadIdx.x;
        float* op = out + (size_t)b * 246016 + 2 * u;
        *(float2*)(op)      = make_float2(Y[0], Y[1]);
        *(float2*)(op + 62) = make_float2(Y[2], Y[3]);
    }
}

extern "C" void kernel_launch(void* const* d_in, const int* in_sizes, int n_in,
                              void* d_out, int out_size) {
    const float* x    = (const float*)d_in[0];   // (64,64,64,64) f32
    const float* filt = (const float*)d_in[1];   // (64,64,3,3)   f32
    float* out = (float*)d_out;                  // (64,64,62,62) f32

    dim3 grid(FPB + 1, 64);                      // (241, 64) = 15424 blocks
    wg_fused<<<grid, 256>>>(x, filt, out);
}